// round 1
// baseline (speedup 1.0000x reference)
#include <cuda_runtime.h>
#include <math.h>

#define MM   16          // B*T
#define NN   5000
#define DIN  64
#define EE   80000
#define HC   128
#define E2   (EE + NN)   // 85000 with self loops
#define ROWS (MM * NN)   // 80000

// ---------------- scratch (no allocations allowed) ----------------
__device__ float g_xl[ROWS * HC];   // 41 MB, node-major: [n*MM + m][128]
__device__ float g_xr[ROWS * HC];
__device__ float g_h [ROWS * HC];   // layer-1 output (node-major)
__device__ int   g_cnt[NN];
__device__ float g_wsum[NN];
__device__ int   g_rowoff[NN + 1];
__device__ int   g_fill[NN];
__device__ float g_selfw[NN];
__device__ int   g_esrc[E2];
__device__ float g_eew[E2];

// ---------------- preprocessing ----------------
__global__ void k_zero() {
    int i = blockIdx.x * blockDim.x + threadIdx.x;
    if (i < NN) { g_cnt[i] = 0; g_wsum[i] = 0.f; }
}

__global__ void k_deg(const int* __restrict__ ei, const float* __restrict__ ew) {
    int e = blockIdx.x * blockDim.x + threadIdx.x;
    if (e < EE) {
        int d = ei[EE + e];
        atomicAdd(&g_cnt[d], 1);
        atomicAdd(&g_wsum[d], ew[e]);
    }
}

// one block, 1024 threads: exclusive scan of (deg+1), self-loop weights
__global__ void k_scan() {
    __shared__ int sums[1024];
    int tid = threadIdx.x;
    int base = tid * 5;
    int loc[5];
    int s = 0;
#pragma unroll
    for (int j = 0; j < 5; j++) {
        int i = base + j;
        int d = (i < NN) ? (g_cnt[i] + 1) : 0;   // +1 for self loop
        loc[j] = s;
        s += d;
    }
    sums[tid] = s;
    __syncthreads();
    for (int off = 1; off < 1024; off <<= 1) {
        int v = (tid >= off) ? sums[tid - off] : 0;
        __syncthreads();
        sums[tid] += v;
        __syncthreads();
    }
    int excl = (tid == 0) ? 0 : sums[tid - 1];
#pragma unroll
    for (int j = 0; j < 5; j++) {
        int i = base + j;
        if (i < NN) {
            int o = excl + loc[j];
            g_rowoff[i] = o;
            g_fill[i]   = o;
            int c = g_cnt[i];
            g_selfw[i] = (c > 0) ? (g_wsum[i] / (float)c) : 0.f;
        }
    }
    if (tid == 1023) g_rowoff[NN] = sums[1023];
}

__global__ void k_scatter(const int* __restrict__ ei, const float* __restrict__ ew) {
    int i = blockIdx.x * blockDim.x + threadIdx.x;
    if (i < EE) {
        int d = ei[EE + i];
        int p = atomicAdd(&g_fill[d], 1);
        g_esrc[p] = ei[i];
        g_eew[p]  = ew[i];
    } else if (i < E2) {
        int n = i - EE;
        int p = atomicAdd(&g_fill[n], 1);
        g_esrc[p] = n;
        g_eew[p]  = g_selfw[n];
    }
}

// ---------------- projections: [xl | xr] = A @ [Wl | Wr] ----------------
// block tile 64 rows x 256 cols, 256 threads, 8x8 microtile, K-chunk 32.
// MAP==1: input rows are (m*NN+n) (the raw x tensor) -> output row n*MM+m.
// IN_H  : read input from g_h instead of the A parameter.
template <int K, int MAP, int IN_H>
__global__ void __launch_bounds__(256) k_gemm(const float* __restrict__ Ain,
                                              const float* __restrict__ Wl,
                                              const float* __restrict__ Wr) {
    __shared__ float As[32][64];
    __shared__ float Bs[32][256];
    const float* __restrict__ A = IN_H ? (const float*)g_h : Ain;

    int tid  = threadIdx.x;
    int row0 = blockIdx.x * 64;
    int tc = tid & 31;       // col group: cols tc*8 .. tc*8+7 (of 256)
    int tr = tid >> 5;       // row group: rows tr*8 .. tr*8+7 (of 64)

    float acc[8][8];
#pragma unroll
    for (int i = 0; i < 8; i++)
#pragma unroll
        for (int j = 0; j < 8; j++) acc[i][j] = 0.f;

    for (int kc = 0; kc < K; kc += 32) {
        // stage A (transposed: As[k][row])
        {
            int r  = tid & 63;
            int kq = tid >> 6;   // 0..3
#pragma unroll
            for (int rep = 0; rep < 2; rep++) {
                int k4 = kq * 8 + rep * 4;
                float4 v = *(const float4*)&A[(row0 + r) * K + kc + k4];
                As[k4 + 0][r] = v.x;
                As[k4 + 1][r] = v.y;
                As[k4 + 2][r] = v.z;
                As[k4 + 3][r] = v.w;
            }
        }
        // stage B = [Wl | Wr] rows kc..kc+31
        {
#pragma unroll
            for (int i = 0; i < 8; i++) {
                int f  = tid + i * 256;       // 0..2047 float4 slots
                int k  = f >> 6;
                int c4 = (f & 63) * 4;
                const float* src = (c4 < 128) ? &Wl[(kc + k) * 128 + c4]
                                              : &Wr[(kc + k) * 128 + (c4 - 128)];
                *(float4*)&Bs[k][c4] = *(const float4*)src;
            }
        }
        __syncthreads();
#pragma unroll
        for (int k = 0; k < 32; k++) {
            float a[8], b[8];
            *(float4*)&a[0] = *(const float4*)&As[k][tr * 8];
            *(float4*)&a[4] = *(const float4*)&As[k][tr * 8 + 4];
            *(float4*)&b[0] = *(const float4*)&Bs[k][tc * 8];
            *(float4*)&b[4] = *(const float4*)&Bs[k][tc * 8 + 4];
#pragma unroll
            for (int i = 0; i < 8; i++)
#pragma unroll
                for (int j = 0; j < 8; j++) acc[i][j] = fmaf(a[i], b[j], acc[i][j]);
        }
        __syncthreads();
    }

    int c = tc * 8;
    float* dstbuf = (c < 128) ? g_xl : g_xr;
    int cc = (c < 128) ? c : (c - 128);
#pragma unroll
    for (int i = 0; i < 8; i++) {
        int r = row0 + tr * 8 + i;
        int orow;
        if (MAP == 1) {
            int m = r / NN;
            int n = r - m * NN;
            orow  = n * MM + m;
        } else {
            orow = r;
        }
        *(float4*)&dstbuf[orow * HC + cc] =
            make_float4(acc[i][0], acc[i][1], acc[i][2], acc[i][3]);
        *(float4*)&dstbuf[orow * HC + cc + 4] =
            make_float4(acc[i][4], acc[i][5], acc[i][6], acc[i][7]);
    }
}

// ---------------- fused edge kernel: gather + online softmax + aggregate ----------------
// one warp per (dst, m). lane owns channels 4*lane..4*lane+3; lanes 0-15 head 0, 16-31 head 1.
// LAYER2: write ELU(out) to d_out in (m,n) order; else write to g_h node-major.
template <int LAYER2>
__global__ void __launch_bounds__(256) k_edge(const float* __restrict__ We,
                                              const float* __restrict__ att,
                                              const float* __restrict__ bias,
                                              float* __restrict__ out) {
    int warp = threadIdx.x >> 5;
    int lane = threadIdx.x & 31;
    int dst  = blockIdx.x >> 1;
    int m    = ((blockIdx.x & 1) << 3) | warp;

    float4 xi = *(const float4*)&g_xr[(dst * MM + m) * HC + lane * 4];
    float4 we = *(const float4*)&We[lane * 4];
    float4 at = *(const float4*)&att[lane * 4];

    float ax = 0.f, ay = 0.f, az = 0.f, aw = 0.f;
    float mx = -1e30f, dn = 0.f;

    int beg = g_rowoff[dst];
    int end = g_rowoff[dst + 1];
    for (int j = beg; j < end; j++) {
        int   s = g_esrc[j];
        float w = g_eew[j];
        float4 xj = *(const float4*)&g_xl[(s * MM + m) * HC + lane * 4];

        float t0 = xi.x + xj.x + w * we.x;
        float t1 = xi.y + xj.y + w * we.y;
        float t2 = xi.z + xj.z + w * we.z;
        float t3 = xi.w + xj.w + w * we.w;
        t0 = (t0 > 0.f) ? t0 : 0.2f * t0;
        t1 = (t1 > 0.f) ? t1 : 0.2f * t1;
        t2 = (t2 > 0.f) ? t2 : 0.2f * t2;
        t3 = (t3 > 0.f) ? t3 : 0.2f * t3;
        float p = t0 * at.x;
        p = fmaf(t1, at.y, p);
        p = fmaf(t2, at.z, p);
        p = fmaf(t3, at.w, p);
        // half-warp (per-head) reduction
        p += __shfl_xor_sync(0xffffffffu, p, 1);
        p += __shfl_xor_sync(0xffffffffu, p, 2);
        p += __shfl_xor_sync(0xffffffffu, p, 4);
        p += __shfl_xor_sync(0xffffffffu, p, 8);

        float nm = fmaxf(mx, p);
        float sc = __expf(mx - nm);
        float e  = __expf(p - nm);
        dn = dn * sc + e;
        ax = fmaf(e, xj.x, ax * sc);
        ay = fmaf(e, xj.y, ay * sc);
        az = fmaf(e, xj.z, az * sc);
        aw = fmaf(e, xj.w, aw * sc);
        mx = nm;
    }

    float inv = 1.f / (dn + 1e-16f);
    float4 b  = *(const float4*)&bias[lane * 4];
    float o0 = ax * inv + b.x;
    float o1 = ay * inv + b.y;
    float o2 = az * inv + b.z;
    float o3 = aw * inv + b.w;
    // ELU epilogue (both layers are followed by ELU in the reference)
    o0 = (o0 > 0.f) ? o0 : (__expf(o0) - 1.f);
    o1 = (o1 > 0.f) ? o1 : (__expf(o1) - 1.f);
    o2 = (o2 > 0.f) ? o2 : (__expf(o2) - 1.f);
    o3 = (o3 > 0.f) ? o3 : (__expf(o3) - 1.f);

    if (LAYER2) {
        *(float4*)&out[(m * NN + dst) * HC + lane * 4] = make_float4(o0, o1, o2, o3);
    } else {
        *(float4*)&g_h[(dst * MM + m) * HC + lane * 4] = make_float4(o0, o1, o2, o3);
    }
}

// ---------------- launch ----------------
extern "C" void kernel_launch(void* const* d_in, const int* in_sizes, int n_in,
                              void* d_out, int out_size) {
    const float* x    = (const float*)d_in[0];
    const int*   ei   = (const int*)d_in[1];
    const float* ew   = (const float*)d_in[2];
    const float* Wl1  = (const float*)d_in[3];
    const float* Wr1  = (const float*)d_in[4];
    const float* att1 = (const float*)d_in[5];
    const float* We1  = (const float*)d_in[6];
    const float* b1   = (const float*)d_in[7];
    const float* Wl2  = (const float*)d_in[8];
    const float* Wr2  = (const float*)d_in[9];
    const float* att2 = (const float*)d_in[10];
    const float* We2  = (const float*)d_in[11];
    const float* b2   = (const float*)d_in[12];
    float* out = (float*)d_out;

    k_zero<<<(NN + 255) / 256, 256>>>();
    k_deg<<<(EE + 255) / 256, 256>>>(ei, ew);
    k_scan<<<1, 1024>>>();
    k_scatter<<<(E2 + 255) / 256, 256>>>(ei, ew);

    // layer 1
    k_gemm<DIN, 1, 0><<<ROWS / 64, 256>>>(x, Wl1, Wr1);
    k_edge<0><<<NN * 2, 256>>>(We1, att1, b1, nullptr);

    // layer 2
    k_gemm<HC, 0, 1><<<ROWS / 64, 256>>>(nullptr, Wl2, Wr2);
    k_edge<1><<<NN * 2, 256>>>(We2, att2, b2, out);
}